// round 7
// baseline (speedup 1.0000x reference)
#include <cuda_runtime.h>
#include <cuda_bf16.h>
#include <cstdint>

// Problem constants
#define NN   40000
#define NE   640000
#define DIM  128
#define DO2  64
#define ELLW 64      // max in-degree capacity (Poisson(16) over 40k nodes: safe)

// ---------------- scratch (device globals; no allocation allowed) ----------
// Feature matrices stored as hi/lo bf16 planes (row-major NN x 128 each).
__device__ __nv_bfloat16 g_xh[NN * DIM],  g_xl[NN * DIM];
__device__ __nv_bfloat16 g_aggh[NN * DIM], g_aggl[NN * DIM];
__device__ __nv_bfloat16 g_h0h[NN * DIM], g_h0l[NN * DIM];
__device__ __nv_bfloat16 g_h1h[NN * DIM], g_h1l[NN * DIM];
__device__ int   g_ell[NN * ELLW];
__device__ int   g_cnt[NN];
__device__ int   g_edge64;
// transposed + bf16-split weights, layout [n][k], k = 0..255 (Wr rows | Ws rows)
__device__ __nv_bfloat16 g_wh0[128 * 256], g_wl0[128 * 256];
__device__ __nv_bfloat16 g_wh1[128 * 256], g_wl1[128 * 256];
__device__ __nv_bfloat16 g_wh2[64 * 256],  g_wl2[64 * 256];

// ---------------- helpers ---------------------------------------------------
__device__ __forceinline__ uint32_t smem_u32(const void* p) {
    uint32_t a;
    asm("{ .reg .u64 t; cvta.to.shared.u64 t, %1; cvt.u32.u64 %0, t; }"
        : "=r"(a) : "l"(p));
    return a;
}

__device__ __forceinline__ void mma_bf16(float* c, const uint32_t* a,
                                         const uint32_t* b) {
    asm volatile(
        "mma.sync.aligned.m16n8k16.row.col.f32.bf16.bf16.f32 "
        "{%0,%1,%2,%3}, {%4,%5,%6,%7}, {%8,%9}, {%0,%1,%2,%3};"
        : "+f"(c[0]), "+f"(c[1]), "+f"(c[2]), "+f"(c[3])
        : "r"(a[0]), "r"(a[1]), "r"(a[2]), "r"(a[3]), "r"(b[0]), "r"(b[1]));
}

__device__ __forceinline__ void ldm4(uint32_t* r, uint32_t addr) {
    asm volatile("ldmatrix.sync.aligned.m8n8.x4.shared.b16 {%0,%1,%2,%3}, [%4];"
                 : "=r"(r[0]), "=r"(r[1]), "=r"(r[2]), "=r"(r[3]) : "r"(addr));
}

// ---------------- edge index dtype detection -------------------------------
__global__ void detect_kernel(const int* __restrict__ ei32) {
    if (blockIdx.x == 0 && threadIdx.x == 0) {
        int is64 = 1;
        #pragma unroll 1
        for (int i = 0; i < 64; i++) {
            if (ei32[2 * i + 1] != 0) { is64 = 0; break; }
        }
        g_edge64 = is64;
    }
}

__global__ void zero_cnt_kernel(int n) {
    int i = blockIdx.x * blockDim.x + threadIdx.x;
    if (i < n) g_cnt[i] = 0;
}

__global__ void build_ell_kernel(const void* __restrict__ ei, int E) {
    int i = blockIdx.x * blockDim.x + threadIdx.x;
    if (i >= E) return;
    int s, d;
    if (g_edge64) {
        const long long* p = (const long long*)ei;
        s = (int)p[i];
        d = (int)p[E + i];
    } else {
        const int* p = (const int*)ei;
        s = p[i];
        d = p[E + i];
    }
    int slot = atomicAdd(&g_cnt[d], 1);
    g_ell[d * ELLW + slot] = s;
}

// ---------------- weight prep: transpose + bf16 hi/lo split ----------------
template <int DO>
__global__ void prep_w_kernel(const float* __restrict__ Wr,
                              const float* __restrict__ Ws,
                              __nv_bfloat16* __restrict__ Wh,
                              __nv_bfloat16* __restrict__ Wl) {
    int i = blockIdx.x * blockDim.x + threadIdx.x;
    if (i >= 256 * DO) return;
    int k = i % 256;
    int n = i / 256;
    float w = (k < 128) ? Wr[(size_t)k * DO + n] : Ws[(size_t)(k - 128) * DO + n];
    __nv_bfloat16 hi = __float2bfloat16(w);
    float lo = w - __bfloat162float(hi);
    Wh[(size_t)n * 256 + k] = hi;
    Wl[(size_t)n * 256 + k] = __float2bfloat16(lo);
}

// ---------------- split x fp32 -> hi/lo bf16 planes ------------------------
__global__ void split_x_kernel(const float4* __restrict__ x4,
                               uint2* __restrict__ xh, uint2* __restrict__ xl,
                               int n4) {
    int i = blockIdx.x * blockDim.x + threadIdx.x;
    if (i >= n4) return;
    float4 v = x4[i];
    __nv_bfloat162 h01 = __floats2bfloat162_rn(v.x, v.y);
    __nv_bfloat162 h23 = __floats2bfloat162_rn(v.z, v.w);
    __nv_bfloat162 l01 = __floats2bfloat162_rn(v.x - __bfloat162float(h01.x),
                                               v.y - __bfloat162float(h01.y));
    __nv_bfloat162 l23 = __floats2bfloat162_rn(v.z - __bfloat162float(h23.x),
                                               v.w - __bfloat162float(h23.y));
    xh[i] = make_uint2(*(uint32_t*)&h01, *(uint32_t*)&h23);
    xl[i] = make_uint2(*(uint32_t*)&l01, *(uint32_t*)&l23);
}

// ---------------- gather aggregation (one warp per node) -------------------
// Inputs/outputs are hi/lo bf16 planes; accumulation in fp32.
__global__ void gather_kernel(const uint2* __restrict__ hi,
                              const uint2* __restrict__ lo,
                              uint2* __restrict__ oh, uint2* __restrict__ ol,
                              int M) {
    int node = blockIdx.x * (blockDim.x >> 5) + (threadIdx.x >> 5);
    if (node >= M) return;
    int lane = threadIdx.x & 31;
    int deg = g_cnt[node];
    const int* __restrict__ idx = g_ell + node * ELLW;
    float4 acc = make_float4(0.f, 0.f, 0.f, 0.f);

    auto addrow = [&](int s) {
        uint2 H = __ldg(&hi[(size_t)s * 32 + lane]);
        uint2 L = __ldg(&lo[(size_t)s * 32 + lane]);
        float2 h01 = __bfloat1622float2(*(__nv_bfloat162*)&H.x);
        float2 h23 = __bfloat1622float2(*(__nv_bfloat162*)&H.y);
        float2 l01 = __bfloat1622float2(*(__nv_bfloat162*)&L.x);
        float2 l23 = __bfloat1622float2(*(__nv_bfloat162*)&L.y);
        acc.x += h01.x + l01.x;
        acc.y += h01.y + l01.y;
        acc.z += h23.x + l23.x;
        acc.w += h23.y + l23.y;
    };

    int i = 0;
    for (; i + 3 < deg; i += 4) {
        int4 s4 = *(const int4*)(idx + i);
        addrow(s4.x); addrow(s4.y); addrow(s4.z); addrow(s4.w);
    }
    for (; i < deg; i++) addrow(idx[i]);

    __nv_bfloat162 h01 = __floats2bfloat162_rn(acc.x, acc.y);
    __nv_bfloat162 h23 = __floats2bfloat162_rn(acc.z, acc.w);
    __nv_bfloat162 l01 = __floats2bfloat162_rn(acc.x - __bfloat162float(h01.x),
                                               acc.y - __bfloat162float(h01.y));
    __nv_bfloat162 l23 = __floats2bfloat162_rn(acc.z - __bfloat162float(h23.x),
                                               acc.w - __bfloat162float(h23.y));
    oh[(size_t)node * 32 + lane] = make_uint2(*(uint32_t*)&h01, *(uint32_t*)&h23);
    ol[(size_t)node * 32 + lane] = make_uint2(*(uint32_t*)&l01, *(uint32_t*)&l23);
}

// ---------------- mma.sync dual GEMM: relu(Aagg@Wr + br + Ah@Ws) -----------
// 3-term split-bf16; sources preconverted to hi/lo planes (fill = pure copy).
// CTA tile 64 x DO (96KB smem for DO=128 -> 2 CTAs/SM). K=256 in 2 chunks.
template <int DO, bool PLANES>
__global__ void __launch_bounds__(256)
mma_gemm_kernel(const __nv_bfloat16* __restrict__ Aah,
                const __nv_bfloat16* __restrict__ Aal,
                const __nv_bfloat16* __restrict__ Ahh,
                const __nv_bfloat16* __restrict__ Ahl,
                const __nv_bfloat16* __restrict__ Wh,
                const __nv_bfloat16* __restrict__ Wl,
                const float* __restrict__ br,
                __nv_bfloat16* __restrict__ Oh, __nv_bfloat16* __restrict__ Ol,
                float* __restrict__ Of, int M) {
    constexpr int WN  = (DO == 128) ? 4 : 2;   // warps along N
    constexpr int WM  = 8 / WN;                // warps along M
    constexpr int RPW = 64 / WM;               // rows per warp tile
    constexpr int AI  = RPW / 16;              // m16 frags per warp
    constexpr int A_HI = 0;
    constexpr int A_LO = 16384;                // A plane: 64x128 bf16 = 16KB
    constexpr int B_HI = 32768;
    constexpr int B_LO = 32768 + DO * 256;

    extern __shared__ char smem[];
    const uint32_t sb = smem_u32(smem);
    const int tid = threadIdx.x;
    const int lane = tid & 31;
    const int wid = tid >> 5;
    const int wm = wid / WN;
    const int wn = wid % WN;
    const int m0 = blockIdx.x * 64;

    float acc[AI][4][4];
    #pragma unroll
    for (int i = 0; i < AI; i++)
        #pragma unroll
        for (int j = 0; j < 4; j++)
            #pragma unroll
            for (int q = 0; q < 4; q++) acc[i][j][q] = 0.f;

    #pragma unroll 1
    for (int ch = 0; ch < 2; ch++) {
        const uint4* __restrict__ Ah4 = (const uint4*)(ch ? Ahh : Aah);
        const uint4* __restrict__ Al4 = (const uint4*)(ch ? Ahl : Aal);
        // ---- fill A: 64 rows x 16 granules(16B) per plane ----
        #pragma unroll
        for (int t = 0; t < 4; t++) {
            int f = tid + t * 256;          // 0..1023
            int row = f >> 4;
            int gi = f & 15;
            uint32_t off = (uint32_t)row * 256u + (uint32_t)((gi ^ (row & 7)) << 4);
            *(uint4*)(smem + A_HI + off) = Ah4[(size_t)(m0 + row) * 16 + gi];
            *(uint4*)(smem + A_LO + off) = Al4[(size_t)(m0 + row) * 16 + gi];
        }
        // ---- fill B: DO rows x 16 granules per plane ----
        #pragma unroll
        for (int t = 0; t < DO / 16; t++) {
            int f = tid + t * 256;
            int n = f >> 4;
            int gi = f & 15;
            uint32_t off = (uint32_t)n * 256u + (uint32_t)((gi ^ (n & 7)) << 4);
            *(uint4*)(smem + B_HI + off) =
                ((const uint4*)Wh)[(size_t)n * 32 + ch * 16 + gi];
            *(uint4*)(smem + B_LO + off) =
                ((const uint4*)Wl)[(size_t)n * 32 + ch * 16 + gi];
        }
        __syncthreads();

        // ---- MMA over 8 k16-steps ----
        #pragma unroll
        for (int ks = 0; ks < 8; ks++) {
            uint32_t ah[AI][4], al[AI][4], bh[2][4], bl[2][4];
            int hc = (lane >> 4) & 1;
            #pragma unroll
            for (int i = 0; i < AI; i++) {
                int r = wm * RPW + i * 16 + (lane & 15);
                uint32_t ad = sb + A_HI + (uint32_t)r * 256u
                            + (uint32_t)(((ks * 2 + hc) ^ (r & 7)) << 4);
                ldm4(ah[i], ad);
                ldm4(al[i], ad + (A_LO - A_HI));
            }
            int nn = (lane & 7) | ((lane & 16) >> 1);
            int hb = (lane >> 3) & 1;
            #pragma unroll
            for (int p = 0; p < 2; p++) {
                int n = wn * 32 + p * 16 + nn;
                uint32_t bd = sb + B_HI + (uint32_t)n * 256u
                            + (uint32_t)(((ks * 2 + hb) ^ (n & 7)) << 4);
                ldm4(bh[p], bd);
                ldm4(bl[p], bd + (B_LO - B_HI));
            }
            #pragma unroll
            for (int i = 0; i < AI; i++)
                #pragma unroll
                for (int j = 0; j < 4; j++) {
                    const uint32_t* bhp = &bh[j >> 1][(j & 1) * 2];
                    const uint32_t* blp = &bl[j >> 1][(j & 1) * 2];
                    mma_bf16(acc[i][j], ah[i], bhp);
                    mma_bf16(acc[i][j], ah[i], blp);
                    mma_bf16(acc[i][j], al[i], bhp);
                }
        }
        __syncthreads();
    }

    // ---- epilogue: + bias, ReLU, store (planes or fp32) ----
    const int cb = wn * 32 + (lane & 3) * 2;
    float2 bias[4];
    #pragma unroll
    for (int j = 0; j < 4; j++) bias[j] = *(const float2*)(br + cb + j * 8);
    #pragma unroll
    for (int i = 0; i < AI; i++) {
        #pragma unroll
        for (int half = 0; half < 2; half++) {
            int r = m0 + wm * RPW + i * 16 + half * 8 + (lane >> 2);
            if (r >= M) continue;
            #pragma unroll
            for (int j = 0; j < 4; j++) {
                float vx = fmaxf(acc[i][j][half * 2 + 0] + bias[j].x, 0.f);
                float vy = fmaxf(acc[i][j][half * 2 + 1] + bias[j].y, 0.f);
                if (PLANES) {
                    __nv_bfloat162 h = __floats2bfloat162_rn(vx, vy);
                    __nv_bfloat162 l = __floats2bfloat162_rn(
                        vx - __bfloat162float(h.x), vy - __bfloat162float(h.y));
                    *(uint32_t*)(Oh + (size_t)r * DO + cb + j * 8) = *(uint32_t*)&h;
                    *(uint32_t*)(Ol + (size_t)r * DO + cb + j * 8) = *(uint32_t*)&l;
                } else {
                    *(float2*)(Of + (size_t)r * DO + cb + j * 8) =
                        make_float2(vx, vy);
                }
            }
        }
    }
}

// ---------------- row-wise log_softmax over 64 cols (in place) -------------
__global__ void logsoftmax_kernel(float* __restrict__ io, int M) {
    int row = blockIdx.x * 8 + (threadIdx.x >> 5);
    if (row >= M) return;
    int lane = threadIdx.x & 31;
    float2* p = (float2*)io + (size_t)row * 32 + lane;
    float2 v = *p;
    float mx = fmaxf(v.x, v.y);
    #pragma unroll
    for (int o = 16; o > 0; o >>= 1)
        mx = fmaxf(mx, __shfl_xor_sync(0xffffffffu, mx, o));
    float s = expf(v.x - mx) + expf(v.y - mx);
    #pragma unroll
    for (int o = 16; o > 0; o >>= 1)
        s += __shfl_xor_sync(0xffffffffu, s, o);
    float lse = mx + logf(s);
    v.x -= lse;
    v.y -= lse;
    *p = v;
}

// ---------------- launch ----------------------------------------------------
extern "C" void kernel_launch(void* const* d_in, const int* in_sizes, int n_in,
                              void* d_out, int out_size) {
    const float* x   = (const float*)d_in[0];
    const void*  ei  = d_in[1];
    const float* Wr0 = (const float*)d_in[2];
    const float* br0 = (const float*)d_in[3];
    const float* Ws0 = (const float*)d_in[4];
    const float* Wr1 = (const float*)d_in[5];
    const float* br1 = (const float*)d_in[6];
    const float* Ws1 = (const float*)d_in[7];
    const float* Wr2 = (const float*)d_in[8];
    const float* br2 = (const float*)d_in[9];
    const float* Ws2 = (const float*)d_in[10];
    float* out = (float*)d_out;

    const int M = NN;
    const int E = NE;

    __nv_bfloat16 *xh, *xl, *aggh, *aggl, *h0h, *h0l, *h1h, *h1l;
    cudaGetSymbolAddress((void**)&xh, g_xh);
    cudaGetSymbolAddress((void**)&xl, g_xl);
    cudaGetSymbolAddress((void**)&aggh, g_aggh);
    cudaGetSymbolAddress((void**)&aggl, g_aggl);
    cudaGetSymbolAddress((void**)&h0h, g_h0h);
    cudaGetSymbolAddress((void**)&h0l, g_h0l);
    cudaGetSymbolAddress((void**)&h1h, g_h1h);
    cudaGetSymbolAddress((void**)&h1l, g_h1l);
    __nv_bfloat16 *wh0, *wl0, *wh1, *wl1, *wh2, *wl2;
    cudaGetSymbolAddress((void**)&wh0, g_wh0);
    cudaGetSymbolAddress((void**)&wl0, g_wl0);
    cudaGetSymbolAddress((void**)&wh1, g_wh1);
    cudaGetSymbolAddress((void**)&wl1, g_wl1);
    cudaGetSymbolAddress((void**)&wh2, g_wh2);
    cudaGetSymbolAddress((void**)&wl2, g_wl2);

    const int smem128 = 32768 + 2 * 128 * 256;   // 98304
    const int smem64  = 32768 + 2 * 64 * 256;    // 65536
    cudaFuncSetAttribute(mma_gemm_kernel<128, true>,
                         cudaFuncAttributeMaxDynamicSharedMemorySize, smem128);
    cudaFuncSetAttribute(mma_gemm_kernel<64, false>,
                         cudaFuncAttributeMaxDynamicSharedMemorySize, smem64);

    // Build ELL adjacency + weight prep + x split
    zero_cnt_kernel<<<(M + 255) / 256, 256>>>(M);
    detect_kernel<<<1, 32>>>((const int*)ei);
    build_ell_kernel<<<(E + 255) / 256, 256>>>(ei, E);
    prep_w_kernel<128><<<(256 * 128 + 255) / 256, 256>>>(Wr0, Ws0, wh0, wl0);
    prep_w_kernel<128><<<(256 * 128 + 255) / 256, 256>>>(Wr1, Ws1, wh1, wl1);
    prep_w_kernel<64><<<(256 * 64 + 255) / 256, 256>>>(Wr2, Ws2, wh2, wl2);
    split_x_kernel<<<(NN * 32 + 255) / 256, 256>>>((const float4*)x,
                                                   (uint2*)xh, (uint2*)xl, NN * 32);

    const int ggrid = M / 64;              // 625 (exact)
    const int agrid = (M + 7) / 8;

    // Layer 0
    gather_kernel<<<agrid, 256>>>((const uint2*)xh, (const uint2*)xl,
                                  (uint2*)aggh, (uint2*)aggl, M);
    mma_gemm_kernel<128, true><<<ggrid, 256, smem128>>>(
        aggh, aggl, xh, xl, wh0, wl0, br0, h0h, h0l, nullptr, M);

    // Layer 1
    gather_kernel<<<agrid, 256>>>((const uint2*)h0h, (const uint2*)h0l,
                                  (uint2*)aggh, (uint2*)aggl, M);
    mma_gemm_kernel<128, true><<<ggrid, 256, smem128>>>(
        aggh, aggl, h0h, h0l, wh1, wl1, br1, h1h, h1l, nullptr, M);

    // Layer 2 + log_softmax
    gather_kernel<<<agrid, 256>>>((const uint2*)h1h, (const uint2*)h1l,
                                  (uint2*)aggh, (uint2*)aggl, M);
    mma_gemm_kernel<64, false><<<ggrid, 256, smem64>>>(
        aggh, aggl, h1h, h1l, wh2, wl2, br2, nullptr, nullptr, out, M);
    logsoftmax_kernel<<<(M + 7) / 8, 256>>>(out, M);
}

// round 8
// speedup vs baseline: 1.1484x; 1.1484x over previous
#include <cuda_runtime.h>
#include <cuda_bf16.h>
#include <cstdint>

// Problem constants
#define NN   40000
#define NE   640000
#define DIM  128
#define DO2  64
#define ELLW 64      // max in-degree capacity (Poisson(16) over 40k nodes: safe)

// ---------------- scratch (device globals; no allocation allowed) ----------
__device__ float g_agg[NN * DIM];   // agg features (L0/L1); agg_u (L2, first 64 cols layout)
__device__ float g_h0[NN * DIM];    // h0; later reused as uv = h1@[Wr2|Ws2]
__device__ float g_h1[NN * DIM];
__device__ int   g_ell[NN * ELLW];
__device__ int   g_cnt[NN];
__device__ int   g_edge64;
// transposed + bf16-split weights, layout [n][k]
__device__ __nv_bfloat16 g_wh0[128 * 256], g_wl0[128 * 256];  // k=256 (Wr|Ws)
__device__ __nv_bfloat16 g_wh1[128 * 256], g_wl1[128 * 256];
__device__ __nv_bfloat16 g_w2h[128 * 128], g_w2l[128 * 128];  // n=[u:64|v:64], k=128

// ---------------- helpers ---------------------------------------------------
__device__ __forceinline__ uint32_t smem_u32(const void* p) {
    uint32_t a;
    asm("{ .reg .u64 t; cvta.to.shared.u64 t, %1; cvt.u32.u64 %0, t; }"
        : "=r"(a) : "l"(p));
    return a;
}

__device__ __forceinline__ void mma_bf16(float* c, const uint32_t* a,
                                         const uint32_t* b) {
    asm volatile(
        "mma.sync.aligned.m16n8k16.row.col.f32.bf16.bf16.f32 "
        "{%0,%1,%2,%3}, {%4,%5,%6,%7}, {%8,%9}, {%0,%1,%2,%3};"
        : "+f"(c[0]), "+f"(c[1]), "+f"(c[2]), "+f"(c[3])
        : "r"(a[0]), "r"(a[1]), "r"(a[2]), "r"(a[3]), "r"(b[0]), "r"(b[1]));
}

__device__ __forceinline__ void ldm4(uint32_t* r, uint32_t addr) {
    asm volatile("ldmatrix.sync.aligned.m8n8.x4.shared.b16 {%0,%1,%2,%3}, [%4];"
                 : "=r"(r[0]), "=r"(r[1]), "=r"(r[2]), "=r"(r[3]) : "r"(addr));
}

// Swizzled smem offset for a 256B-row bf16 tile (k0 = element col, mult of 4).
__device__ __forceinline__ uint32_t sw_off(int r, int k0) {
    return (uint32_t)r * 256u + ((uint32_t)(((k0 >> 3) ^ (r & 7)) << 4))
         + (uint32_t)((k0 & 4) << 1);
}

// ---------------- edge index dtype detection -------------------------------
__global__ void detect_kernel(const int* __restrict__ ei32) {
    if (blockIdx.x == 0 && threadIdx.x == 0) {
        int is64 = 1;
        #pragma unroll 1
        for (int i = 0; i < 64; i++) {
            if (ei32[2 * i + 1] != 0) { is64 = 0; break; }
        }
        g_edge64 = is64;
    }
}

__global__ void zero_cnt_kernel(int n) {
    int i = blockIdx.x * blockDim.x + threadIdx.x;
    if (i < n) g_cnt[i] = 0;
}

__global__ void build_ell_kernel(const void* __restrict__ ei, int E) {
    int i = blockIdx.x * blockDim.x + threadIdx.x;
    if (i >= E) return;
    int s, d;
    if (g_edge64) {
        const long long* p = (const long long*)ei;
        s = (int)p[i];
        d = (int)p[E + i];
    } else {
        const int* p = (const int*)ei;
        s = p[i];
        d = p[E + i];
    }
    int slot = atomicAdd(&g_cnt[d], 1);
    g_ell[d * ELLW + slot] = s;
}

// ---------------- fused weight prep (all 3 layers, one launch) -------------
// L0/L1: [n][k], k in [0,256): k<128 -> Wr[k][n] else Ws[k-128][n]  (DO=128)
// L2:    [n][k], k in [0,128): n<64 -> Wr2[k][n] else Ws2[k][n-64]  (concat N)
__global__ void prep_all_kernel(const float* __restrict__ Wr0,
                                const float* __restrict__ Ws0,
                                const float* __restrict__ Wr1,
                                const float* __restrict__ Ws1,
                                const float* __restrict__ Wr2,
                                const float* __restrict__ Ws2) {
    int i = blockIdx.x * blockDim.x + threadIdx.x;
    float w;
    __nv_bfloat16* Wh;
    __nv_bfloat16* Wl;
    size_t off;
    if (i < 65536) {
        int j = i & 32767;
        int k = j % 256;
        int n = j / 256;
        const float* Wr = (i < 32768) ? Wr0 : Wr1;
        const float* Ws = (i < 32768) ? Ws0 : Ws1;
        w = (k < 128) ? Wr[(size_t)k * 128 + n] : Ws[(size_t)(k - 128) * 128 + n];
        Wh = (i < 32768) ? g_wh0 : g_wh1;
        Wl = (i < 32768) ? g_wl0 : g_wl1;
        off = (size_t)n * 256 + k;
    } else if (i < 65536 + 16384) {
        int j = i - 65536;
        int k = j % 128;
        int n = j / 128;
        w = (n < 64) ? Wr2[(size_t)k * 64 + n] : Ws2[(size_t)k * 64 + (n - 64)];
        Wh = g_w2h;
        Wl = g_w2l;
        off = (size_t)n * 128 + k;
    } else {
        return;
    }
    __nv_bfloat16 hi = __float2bfloat16(w);
    float lo = w - __bfloat162float(hi);
    Wh[off] = hi;
    Wl[off] = __float2bfloat16(lo);
}

// ---------------- gather aggregation, 128-dim (one warp per node) ----------
__global__ void gather_kernel(const float4* __restrict__ h4,
                              float4* __restrict__ agg, int M) {
    int node = blockIdx.x * (blockDim.x >> 5) + (threadIdx.x >> 5);
    if (node >= M) return;
    int lane = threadIdx.x & 31;
    int deg = g_cnt[node];
    const int* __restrict__ idx = g_ell + node * ELLW;
    float4 acc = make_float4(0.f, 0.f, 0.f, 0.f);
    int i = 0;
    for (; i + 3 < deg; i += 4) {
        int4 s4 = *(const int4*)(idx + i);
        float4 v0 = __ldg(&h4[(size_t)s4.x * 32 + lane]);
        float4 v1 = __ldg(&h4[(size_t)s4.y * 32 + lane]);
        float4 v2 = __ldg(&h4[(size_t)s4.z * 32 + lane]);
        float4 v3 = __ldg(&h4[(size_t)s4.w * 32 + lane]);
        acc.x += (v0.x + v1.x) + (v2.x + v3.x);
        acc.y += (v0.y + v1.y) + (v2.y + v3.y);
        acc.z += (v0.z + v1.z) + (v2.z + v3.z);
        acc.w += (v0.w + v1.w) + (v2.w + v3.w);
    }
    for (; i < deg; i++) {
        int s0 = idx[i];
        float4 v0 = __ldg(&h4[(size_t)s0 * 32 + lane]);
        acc.x += v0.x; acc.y += v0.y; acc.z += v0.z; acc.w += v0.w;
    }
    agg[(size_t)node * 32 + lane] = acc;
}

// ---------------- gather of u (64-dim), two nodes per warp -----------------
// uv rows: 128 floats; u = cols [0,64). Output agg_u rows: 64 floats.
__global__ void gather_u_kernel(const float4* __restrict__ uv4,
                                float4* __restrict__ aggu, int M) {
    int warp = blockIdx.x * (blockDim.x >> 5) + (threadIdx.x >> 5);
    int lane = threadIdx.x & 31;
    int node = warp * 2 + (lane >> 4);
    if (node >= M) return;
    int l = lane & 15;
    int deg = g_cnt[node];
    const int* __restrict__ idx = g_ell + node * ELLW;
    float4 acc = make_float4(0.f, 0.f, 0.f, 0.f);
    int i = 0;
    for (; i + 3 < deg; i += 4) {
        int s0 = idx[i], s1 = idx[i + 1], s2 = idx[i + 2], s3 = idx[i + 3];
        float4 v0 = __ldg(&uv4[(size_t)s0 * 32 + l]);
        float4 v1 = __ldg(&uv4[(size_t)s1 * 32 + l]);
        float4 v2 = __ldg(&uv4[(size_t)s2 * 32 + l]);
        float4 v3 = __ldg(&uv4[(size_t)s3 * 32 + l]);
        acc.x += (v0.x + v1.x) + (v2.x + v3.x);
        acc.y += (v0.y + v1.y) + (v2.y + v3.y);
        acc.z += (v0.z + v1.z) + (v2.z + v3.z);
        acc.w += (v0.w + v1.w) + (v2.w + v3.w);
    }
    for (; i < deg; i++) {
        float4 v0 = __ldg(&uv4[(size_t)idx[i] * 32 + l]);
        acc.x += v0.x; acc.y += v0.y; acc.z += v0.z; acc.w += v0.w;
    }
    aggu[(size_t)node * 16 + l] = acc;
}

// ---------------- mma.sync GEMM (split-bf16, 3-term) -----------------------
// CHUNKS=2: C = relu(A0@W[0:128] + A1@W[128:256] + br)   (layers 0/1)
// CHUNKS=1: C = A0@W                                     (layer 2, raw)
template <int DO, int CHUNKS, bool RELU>
__global__ void __launch_bounds__(256)
mma_gemm_kernel(const float* __restrict__ A0, const float* __restrict__ A1,
                const __nv_bfloat16* __restrict__ Wh,
                const __nv_bfloat16* __restrict__ Wl,
                const float* __restrict__ br, float* __restrict__ C, int M) {
    constexpr int KTOT = CHUNKS * 128;
    constexpr int WN = DO / 32;             // warps along N (4 for DO=128)
    constexpr int THREADS = 64 * WN;
    constexpr int A_HI = 0;
    constexpr int A_LO = 32768;             // A chunk: 128x128 bf16 = 32KB
    constexpr int B_HI = 65536;
    constexpr int B_LO = 65536 + DO * 256;

    extern __shared__ char smem[];
    const uint32_t sb = smem_u32(smem);
    const int tid = threadIdx.x;
    const int lane = tid & 31;
    const int wid = tid >> 5;
    const int wm = wid / WN;                // 0..1
    const int wn = wid % WN;
    const int m0 = blockIdx.x * 128;

    float acc[4][4][4];
    #pragma unroll
    for (int i = 0; i < 4; i++)
        #pragma unroll
        for (int j = 0; j < 4; j++)
            #pragma unroll
            for (int q = 0; q < 4; q++) acc[i][j][q] = 0.f;

    #pragma unroll 1
    for (int ch = 0; ch < CHUNKS; ch++) {
        const float* __restrict__ Asrc = ch ? A1 : A0;

        // ---- fill A (fp32 -> bf16 hi/lo, swizzled) ----
        #pragma unroll
        for (int t = 0; t < 4096 / THREADS; t++) {
            int f = tid + t * THREADS;
            int row = f >> 5;
            int k0 = (f & 31) * 4;
            int gm = m0 + row;
            float4 v = make_float4(0.f, 0.f, 0.f, 0.f);
            if (gm < M) v = *(const float4*)(Asrc + (size_t)gm * DIM + k0);
            __nv_bfloat162 h01 = __floats2bfloat162_rn(v.x, v.y);
            __nv_bfloat162 h23 = __floats2bfloat162_rn(v.z, v.w);
            float lx = v.x - __bfloat162float(h01.x);
            float ly = v.y - __bfloat162float(h01.y);
            float lz = v.z - __bfloat162float(h23.x);
            float lw = v.w - __bfloat162float(h23.y);
            __nv_bfloat162 l01 = __floats2bfloat162_rn(lx, ly);
            __nv_bfloat162 l23 = __floats2bfloat162_rn(lz, lw);
            uint32_t off = sw_off(row, k0);
            *(uint2*)(smem + A_HI + off) =
                make_uint2(*(uint32_t*)&h01, *(uint32_t*)&h23);
            *(uint2*)(smem + A_LO + off) =
                make_uint2(*(uint32_t*)&l01, *(uint32_t*)&l23);
        }
        // ---- fill B (preconverted bf16 hi/lo, swizzled) ----
        #pragma unroll
        for (int t = 0; t < (DO * 32) / THREADS; t++) {
            int f = tid + t * THREADS;
            int n = f >> 5;
            int k0 = (f & 31) * 4;
            uint2 vh = *(const uint2*)(Wh + (size_t)n * KTOT + ch * 128 + k0);
            uint2 vl = *(const uint2*)(Wl + (size_t)n * KTOT + ch * 128 + k0);
            uint32_t off = sw_off(n, k0);
            *(uint2*)(smem + B_HI + off) = vh;
            *(uint2*)(smem + B_LO + off) = vl;
        }
        __syncthreads();

        // ---- MMA over 8 k16-steps ----
        #pragma unroll
        for (int ks = 0; ks < 8; ks++) {
            uint32_t ah[4][4], al[4][4], bh[2][4], bl[2][4];
            int ra = wm * 64 + (lane & 15);
            int hc = (lane >> 4) & 1;
            #pragma unroll
            for (int i = 0; i < 4; i++) {
                int r = ra + i * 16;
                uint32_t ad = sb + A_HI + (uint32_t)r * 256
                            + (uint32_t)((((ks * 2 + hc) ^ (r & 7))) << 4);
                ldm4(ah[i], ad);
                ldm4(al[i], ad + (A_LO - A_HI));
            }
            int nn = (lane & 7) | ((lane & 16) >> 1);
            int hb = (lane >> 3) & 1;
            #pragma unroll
            for (int p = 0; p < 2; p++) {
                int n = wn * 32 + p * 16 + nn;
                uint32_t bd = sb + B_HI + (uint32_t)n * 256
                            + (uint32_t)((((ks * 2 + hb) ^ (n & 7))) << 4);
                ldm4(bh[p], bd);
                ldm4(bl[p], bd + (B_LO - B_HI));
            }
            #pragma unroll
            for (int i = 0; i < 4; i++)
                #pragma unroll
                for (int j = 0; j < 4; j++) {
                    const uint32_t* bhp = &bh[j >> 1][(j & 1) * 2];
                    const uint32_t* blp = &bl[j >> 1][(j & 1) * 2];
                    mma_bf16(acc[i][j], ah[i], bhp);
                    mma_bf16(acc[i][j], ah[i], blp);
                    mma_bf16(acc[i][j], al[i], bhp);
                }
        }
        __syncthreads();
    }

    // ---- epilogue ----
    const int cb = wn * 32 + (lane & 3) * 2;
    float2 bias[4];
    if (RELU) {
        #pragma unroll
        for (int j = 0; j < 4; j++) bias[j] = *(const float2*)(br + cb + j * 8);
    }
    const int rbase = m0 + wm * 64 + (lane >> 2);
    #pragma unroll
    for (int i = 0; i < 4; i++) {
        #pragma unroll
        for (int half = 0; half < 2; half++) {
            int r = rbase + i * 16 + half * 8;
            if (r < M) {
                float* outp = C + (size_t)r * DO;
                #pragma unroll
                for (int j = 0; j < 4; j++) {
                    float vx = acc[i][j][half * 2 + 0];
                    float vy = acc[i][j][half * 2 + 1];
                    if (RELU) {
                        vx = fmaxf(vx + bias[j].x, 0.f);
                        vy = fmaxf(vy + bias[j].y, 0.f);
                    }
                    *(float2*)(outp + cb + j * 8) = make_float2(vx, vy);
                }
            }
        }
    }
}

// ---------------- fused final: relu(agg_u + br2 + v) then log_softmax ------
__global__ void final_kernel(const float* __restrict__ aggu,
                             const float* __restrict__ uv,
                             const float* __restrict__ br,
                             float* __restrict__ out, int M) {
    int row = blockIdx.x * 8 + (threadIdx.x >> 5);
    if (row >= M) return;
    int lane = threadIdx.x & 31;
    float2 u = *(const float2*)(aggu + (size_t)row * 64 + lane * 2);
    float2 w = *(const float2*)(uv + (size_t)row * 128 + 64 + lane * 2);
    float2 b = *(const float2*)(br + lane * 2);
    float vx = fmaxf(u.x + w.x + b.x, 0.f);
    float vy = fmaxf(u.y + w.y + b.y, 0.f);
    float mx = fmaxf(vx, vy);
    #pragma unroll
    for (int o = 16; o > 0; o >>= 1)
        mx = fmaxf(mx, __shfl_xor_sync(0xffffffffu, mx, o));
    float s = expf(vx - mx) + expf(vy - mx);
    #pragma unroll
    for (int o = 16; o > 0; o >>= 1)
        s += __shfl_xor_sync(0xffffffffu, s, o);
    float lse = mx + logf(s);
    *(float2*)(out + (size_t)row * 64 + lane * 2) =
        make_float2(vx - lse, vy - lse);
}

// ---------------- launch ----------------------------------------------------
extern "C" void kernel_launch(void* const* d_in, const int* in_sizes, int n_in,
                              void* d_out, int out_size) {
    const float* x   = (const float*)d_in[0];
    const void*  ei  = d_in[1];
    const float* Wr0 = (const float*)d_in[2];
    const float* br0 = (const float*)d_in[3];
    const float* Ws0 = (const float*)d_in[4];
    const float* Wr1 = (const float*)d_in[5];
    const float* br1 = (const float*)d_in[6];
    const float* Ws1 = (const float*)d_in[7];
    const float* Wr2 = (const float*)d_in[8];
    const float* br2 = (const float*)d_in[9];
    const float* Ws2 = (const float*)d_in[10];
    float* out = (float*)d_out;

    const int M = NN;
    const int E = NE;

    float *agg, *h0, *h1;
    cudaGetSymbolAddress((void**)&agg, g_agg);
    cudaGetSymbolAddress((void**)&h0, g_h0);
    cudaGetSymbolAddress((void**)&h1, g_h1);
    __nv_bfloat16 *wh0, *wl0, *wh1, *wl1, *w2h, *w2l;
    cudaGetSymbolAddress((void**)&wh0, g_wh0);
    cudaGetSymbolAddress((void**)&wl0, g_wl0);
    cudaGetSymbolAddress((void**)&wh1, g_wh1);
    cudaGetSymbolAddress((void**)&wl1, g_wl1);
    cudaGetSymbolAddress((void**)&w2h, g_w2h);
    cudaGetSymbolAddress((void**)&w2l, g_w2l);

    const int smemSz = 65536 + 2 * 128 * 256;   // 131072 (both variants)
    cudaFuncSetAttribute(mma_gemm_kernel<128, 2, true>,
                         cudaFuncAttributeMaxDynamicSharedMemorySize, smemSz);
    cudaFuncSetAttribute(mma_gemm_kernel<128, 1, false>,
                         cudaFuncAttributeMaxDynamicSharedMemorySize, smemSz);

    // Build ELL adjacency + fused weight prep
    zero_cnt_kernel<<<(M + 255) / 256, 256>>>(M);
    detect_kernel<<<1, 32>>>((const int*)ei);
    build_ell_kernel<<<(E + 255) / 256, 256>>>(ei, E);
    prep_all_kernel<<<(65536 + 16384 + 255) / 256, 256>>>(Wr0, Ws0, Wr1, Ws1,
                                                          Wr2, Ws2);

    const int ggrid = (M + 127) / 128;     // 313
    const int agrid = (M + 7) / 8;         // 8 warps/block, 1 node/warp

    // Layer 0: x -> h0
    gather_kernel<<<agrid, 256>>>((const float4*)x, (float4*)agg, M);
    mma_gemm_kernel<128, 2, true><<<ggrid, 256, smemSz>>>(
        agg, x, wh0, wl0, br0, h0, M);

    // Layer 1: h0 -> h1
    gather_kernel<<<agrid, 256>>>((const float4*)h0, (float4*)agg, M);
    mma_gemm_kernel<128, 2, true><<<ggrid, 256, smemSz>>>(
        agg, h0, wh1, wl1, br1, h1, M);

    // Layer 2: uv = h1@[Wr2|Ws2]; gather u (64-dim); fused epilogue+softmax
    mma_gemm_kernel<128, 1, false><<<ggrid, 256, smemSz>>>(
        h1, nullptr, w2h, w2l, nullptr, h0 /*uv*/, M);
    gather_u_kernel<<<(M / 2 + 7) / 8, 256>>>((const float4*)h0, (float4*)agg, M);
    final_kernel<<<(M + 7) / 8, 256>>>(agg, h0, br2, out, M);
}

// round 9
// speedup vs baseline: 1.1564x; 1.0070x over previous
#include <cuda_runtime.h>
#include <cuda_bf16.h>
#include <cstdint>

// Problem constants
#define NN   40000
#define NE   640000
#define DIM  128
#define DO2  64
#define ELLW 64      // max in-degree capacity (Poisson(16) over 40k nodes: safe)

// ---------------- scratch (device globals; no allocation allowed) ----------
__device__ float g_agg[NN * DIM];   // agg features (L0/L1); agg_u (L2, 64-wide)
__device__ float g_h0[NN * DIM];    // h0; later reused as uv = h1@[Wr2|Ws2]
__device__ float g_h1[NN * DIM];
__device__ int   g_ell[NN * ELLW];
__device__ int   g_cnt[NN];
__device__ int   g_edge64;
// transposed + bf16-split weights, layout [n][k]
__device__ __nv_bfloat16 g_wh0[128 * 256], g_wl0[128 * 256];  // k=256 (Wr|Ws)
__device__ __nv_bfloat16 g_wh1[128 * 256], g_wl1[128 * 256];
__device__ __nv_bfloat16 g_w2h[128 * 128], g_w2l[128 * 128];  // n=[u:64|v:64], k=128

// ---------------- helpers ---------------------------------------------------
__device__ __forceinline__ uint32_t smem_u32(const void* p) {
    uint32_t a;
    asm("{ .reg .u64 t; cvta.to.shared.u64 t, %1; cvt.u32.u64 %0, t; }"
        : "=r"(a) : "l"(p));
    return a;
}

__device__ __forceinline__ void mma_bf16(float* c, const uint32_t* a,
                                         const uint32_t* b) {
    asm volatile(
        "mma.sync.aligned.m16n8k16.row.col.f32.bf16.bf16.f32 "
        "{%0,%1,%2,%3}, {%4,%5,%6,%7}, {%8,%9}, {%0,%1,%2,%3};"
        : "+f"(c[0]), "+f"(c[1]), "+f"(c[2]), "+f"(c[3])
        : "r"(a[0]), "r"(a[1]), "r"(a[2]), "r"(a[3]), "r"(b[0]), "r"(b[1]));
}

__device__ __forceinline__ void ldm4(uint32_t* r, uint32_t addr) {
    asm volatile("ldmatrix.sync.aligned.m8n8.x4.shared.b16 {%0,%1,%2,%3}, [%4];"
                 : "=r"(r[0]), "=r"(r[1]), "=r"(r[2]), "=r"(r[3]) : "r"(addr));
}

// Swizzled smem offset for a 256B-row bf16 tile (k0 = element col, mult of 4).
__device__ __forceinline__ uint32_t sw_off(int r, int k0) {
    return (uint32_t)r * 256u + ((uint32_t)(((k0 >> 3) ^ (r & 7)) << 4))
         + (uint32_t)((k0 & 4) << 1);
}

// ---------------- edge index dtype detection -------------------------------
__global__ void detect_kernel(const int* __restrict__ ei32) {
    if (blockIdx.x == 0 && threadIdx.x == 0) {
        int is64 = 1;
        #pragma unroll 1
        for (int i = 0; i < 64; i++) {
            if (ei32[2 * i + 1] != 0) { is64 = 0; break; }
        }
        g_edge64 = is64;
    }
}

__global__ void zero_cnt_kernel(int n) {
    int i = blockIdx.x * blockDim.x + threadIdx.x;
    if (i < n) g_cnt[i] = 0;
}

__global__ void build_ell_kernel(const void* __restrict__ ei, int E) {
    int i = blockIdx.x * blockDim.x + threadIdx.x;
    if (i >= E) return;
    int s, d;
    if (g_edge64) {
        const long long* p = (const long long*)ei;
        s = (int)p[i];
        d = (int)p[E + i];
    } else {
        const int* p = (const int*)ei;
        s = p[i];
        d = p[E + i];
    }
    int slot = atomicAdd(&g_cnt[d], 1);
    g_ell[d * ELLW + slot] = s;
}

// ---------------- fused weight prep (all 3 layers, one launch) -------------
__global__ void prep_all_kernel(const float* __restrict__ Wr0,
                                const float* __restrict__ Ws0,
                                const float* __restrict__ Wr1,
                                const float* __restrict__ Ws1,
                                const float* __restrict__ Wr2,
                                const float* __restrict__ Ws2) {
    int i = blockIdx.x * blockDim.x + threadIdx.x;
    float w;
    __nv_bfloat16* Wh;
    __nv_bfloat16* Wl;
    size_t off;
    if (i < 65536) {
        int j = i & 32767;
        int k = j % 256;
        int n = j / 256;
        const float* Wr = (i < 32768) ? Wr0 : Wr1;
        const float* Ws = (i < 32768) ? Ws0 : Ws1;
        w = (k < 128) ? Wr[(size_t)k * 128 + n] : Ws[(size_t)(k - 128) * 128 + n];
        Wh = (i < 32768) ? g_wh0 : g_wh1;
        Wl = (i < 32768) ? g_wl0 : g_wl1;
        off = (size_t)n * 256 + k;
    } else if (i < 65536 + 16384) {
        int j = i - 65536;
        int k = j % 128;
        int n = j / 128;
        w = (n < 64) ? Wr2[(size_t)k * 64 + n] : Ws2[(size_t)k * 64 + (n - 64)];
        Wh = g_w2h;
        Wl = g_w2l;
        off = (size_t)n * 128 + k;
    } else {
        return;
    }
    __nv_bfloat16 hi = __float2bfloat16(w);
    float lo = w - __bfloat162float(hi);
    Wh[off] = hi;
    Wl[off] = __float2bfloat16(lo);
}

// ---------------- gather aggregation, 128-dim (one warp per node) ----------
__global__ void gather_kernel(const float4* __restrict__ h4,
                              float4* __restrict__ agg, int M) {
    int node = blockIdx.x * (blockDim.x >> 5) + (threadIdx.x >> 5);
    if (node >= M) return;
    int lane = threadIdx.x & 31;
    int deg = g_cnt[node];
    const int* __restrict__ idx = g_ell + node * ELLW;
    float4 acc = make_float4(0.f, 0.f, 0.f, 0.f);
    int i = 0;
    for (; i + 3 < deg; i += 4) {
        int4 s4 = *(const int4*)(idx + i);
        float4 v0 = __ldg(&h4[(size_t)s4.x * 32 + lane]);
        float4 v1 = __ldg(&h4[(size_t)s4.y * 32 + lane]);
        float4 v2 = __ldg(&h4[(size_t)s4.z * 32 + lane]);
        float4 v3 = __ldg(&h4[(size_t)s4.w * 32 + lane]);
        acc.x += (v0.x + v1.x) + (v2.x + v3.x);
        acc.y += (v0.y + v1.y) + (v2.y + v3.y);
        acc.z += (v0.z + v1.z) + (v2.z + v3.z);
        acc.w += (v0.w + v1.w) + (v2.w + v3.w);
    }
    for (; i < deg; i++) {
        int s0 = idx[i];
        float4 v0 = __ldg(&h4[(size_t)s0 * 32 + lane]);
        acc.x += v0.x; acc.y += v0.y; acc.z += v0.z; acc.w += v0.w;
    }
    agg[(size_t)node * 32 + lane] = acc;
}

// ---------------- gather of u (64-dim), two nodes per warp -----------------
__global__ void gather_u_kernel(const float4* __restrict__ uv4,
                                float4* __restrict__ aggu, int M) {
    int warp = blockIdx.x * (blockDim.x >> 5) + (threadIdx.x >> 5);
    int lane = threadIdx.x & 31;
    int node = warp * 2 + (lane >> 4);
    if (node >= M) return;
    int l = lane & 15;
    int deg = g_cnt[node];
    const int* __restrict__ idx = g_ell + node * ELLW;
    float4 acc = make_float4(0.f, 0.f, 0.f, 0.f);
    int i = 0;
    for (; i + 3 < deg; i += 4) {
        int s0 = idx[i], s1 = idx[i + 1], s2 = idx[i + 2], s3 = idx[i + 3];
        float4 v0 = __ldg(&uv4[(size_t)s0 * 32 + l]);
        float4 v1 = __ldg(&uv4[(size_t)s1 * 32 + l]);
        float4 v2 = __ldg(&uv4[(size_t)s2 * 32 + l]);
        float4 v3 = __ldg(&uv4[(size_t)s3 * 32 + l]);
        acc.x += (v0.x + v1.x) + (v2.x + v3.x);
        acc.y += (v0.y + v1.y) + (v2.y + v3.y);
        acc.z += (v0.z + v1.z) + (v2.z + v3.z);
        acc.w += (v0.w + v1.w) + (v2.w + v3.w);
    }
    for (; i < deg; i++) {
        float4 v0 = __ldg(&uv4[(size_t)idx[i] * 32 + l]);
        acc.x += v0.x; acc.y += v0.y; acc.z += v0.z; acc.w += v0.w;
    }
    aggu[(size_t)node * 16 + l] = acc;
}

// ---------------- mma.sync GEMM (split-bf16, 3-term, 2 CTAs/SM) ------------
// smem: Ahi 32K | Alo 32K | B 32K (single plane, hi then lo swapped in).
// Per chunk: fill(Ahi,Alo,Bhi); MMA{hi*Bhi, lo*Bhi}; fill(Blo); MMA{hi*Blo}.
// CHUNKS=2: C = relu(A0@W[0:128] + A1@W[128:256] + br)   (layers 0/1)
// CHUNKS=1: C = A0@W                                     (layer 2, raw)
template <int DO, int CHUNKS, bool RELU>
__global__ void __launch_bounds__(256, 2)
mma_gemm_kernel(const float* __restrict__ A0, const float* __restrict__ A1,
                const __nv_bfloat16* __restrict__ Wh,
                const __nv_bfloat16* __restrict__ Wl,
                const float* __restrict__ br, float* __restrict__ C, int M) {
    constexpr int KTOT = CHUNKS * 128;
    constexpr int WN = DO / 32;             // warps along N (4 for DO=128)
    constexpr int THREADS = 256;
    constexpr int A_HI = 0;
    constexpr int A_LO = 32768;
    constexpr int B_SM = 65536;             // single 32KB B plane

    extern __shared__ char smem[];
    const uint32_t sb = smem_u32(smem);
    const int tid = threadIdx.x;
    const int lane = tid & 31;
    const int wid = tid >> 5;
    const int wm = wid / WN;                // 0..1
    const int wn = wid % WN;
    const int m0 = blockIdx.x * 128;

    float acc[4][4][4];
    #pragma unroll
    for (int i = 0; i < 4; i++)
        #pragma unroll
        for (int j = 0; j < 4; j++)
            #pragma unroll
            for (int q = 0; q < 4; q++) acc[i][j][q] = 0.f;

    // B plane fill: 16B vectors, granule g = 8 bf16
    auto fillB = [&](const __nv_bfloat16* __restrict__ W, int ch) {
        #pragma unroll
        for (int t = 0; t < (DO * 16) / THREADS; t++) {
            int f = tid + t * THREADS;
            int n = f >> 4;
            int g = f & 15;
            uint32_t off = (uint32_t)n * 256u + (uint32_t)((g ^ (n & 7)) << 4);
            *(uint4*)(smem + B_SM + off) =
                *(const uint4*)(W + (size_t)n * KTOT + ch * 128 + g * 8);
        }
    };

    #pragma unroll 1
    for (int ch = 0; ch < CHUNKS; ch++) {
        const float* __restrict__ Asrc = ch ? A1 : A0;

        // ---- fill A (fp32 -> bf16 hi/lo, swizzled) + B hi plane ----
        #pragma unroll
        for (int t = 0; t < 4096 / THREADS; t++) {
            int f = tid + t * THREADS;
            int row = f >> 5;
            int k0 = (f & 31) * 4;
            int gm = m0 + row;
            float4 v = make_float4(0.f, 0.f, 0.f, 0.f);
            if (gm < M) v = *(const float4*)(Asrc + (size_t)gm * DIM + k0);
            __nv_bfloat162 h01 = __floats2bfloat162_rn(v.x, v.y);
            __nv_bfloat162 h23 = __floats2bfloat162_rn(v.z, v.w);
            float lx = v.x - __bfloat162float(h01.x);
            float ly = v.y - __bfloat162float(h01.y);
            float lz = v.z - __bfloat162float(h23.x);
            float lw = v.w - __bfloat162float(h23.y);
            __nv_bfloat162 l01 = __floats2bfloat162_rn(lx, ly);
            __nv_bfloat162 l23 = __floats2bfloat162_rn(lz, lw);
            uint32_t off = sw_off(row, k0);
            *(uint2*)(smem + A_HI + off) =
                make_uint2(*(uint32_t*)&h01, *(uint32_t*)&h23);
            *(uint2*)(smem + A_LO + off) =
                make_uint2(*(uint32_t*)&l01, *(uint32_t*)&l23);
        }
        fillB(Wh, ch);
        __syncthreads();

        // ---- MMA region 1: Ahi*Bhi + Alo*Bhi ----
        #pragma unroll
        for (int ks = 0; ks < 8; ks++) {
            uint32_t ah[4][4], al[4][4], bb[2][4];
            int ra = wm * 64 + (lane & 15);
            int hc = (lane >> 4) & 1;
            #pragma unroll
            for (int i = 0; i < 4; i++) {
                int r = ra + i * 16;
                uint32_t ad = sb + A_HI + (uint32_t)r * 256
                            + (uint32_t)((((ks * 2 + hc) ^ (r & 7))) << 4);
                ldm4(ah[i], ad);
                ldm4(al[i], ad + (A_LO - A_HI));
            }
            int nn = (lane & 7) | ((lane & 16) >> 1);
            int hb = (lane >> 3) & 1;
            #pragma unroll
            for (int p = 0; p < 2; p++) {
                int n = wn * 32 + p * 16 + nn;
                uint32_t bd = sb + B_SM + (uint32_t)n * 256
                            + (uint32_t)((((ks * 2 + hb) ^ (n & 7))) << 4);
                ldm4(bb[p], bd);
            }
            #pragma unroll
            for (int i = 0; i < 4; i++)
                #pragma unroll
                for (int j = 0; j < 4; j++) {
                    const uint32_t* bp = &bb[j >> 1][(j & 1) * 2];
                    mma_bf16(acc[i][j], ah[i], bp);
                    mma_bf16(acc[i][j], al[i], bp);
                }
        }
        __syncthreads();

        // ---- swap in B lo plane ----
        fillB(Wl, ch);
        __syncthreads();

        // ---- MMA region 2: Ahi*Blo ----
        #pragma unroll
        for (int ks = 0; ks < 8; ks++) {
            uint32_t ah[4][4], bb[2][4];
            int ra = wm * 64 + (lane & 15);
            int hc = (lane >> 4) & 1;
            #pragma unroll
            for (int i = 0; i < 4; i++) {
                int r = ra + i * 16;
                uint32_t ad = sb + A_HI + (uint32_t)r * 256
                            + (uint32_t)((((ks * 2 + hc) ^ (r & 7))) << 4);
                ldm4(ah[i], ad);
            }
            int nn = (lane & 7) | ((lane & 16) >> 1);
            int hb = (lane >> 3) & 1;
            #pragma unroll
            for (int p = 0; p < 2; p++) {
                int n = wn * 32 + p * 16 + nn;
                uint32_t bd = sb + B_SM + (uint32_t)n * 256
                            + (uint32_t)((((ks * 2 + hb) ^ (n & 7))) << 4);
                ldm4(bb[p], bd);
            }
            #pragma unroll
            for (int i = 0; i < 4; i++)
                #pragma unroll
                for (int j = 0; j < 4; j++)
                    mma_bf16(acc[i][j], ah[i], &bb[j >> 1][(j & 1) * 2]);
        }
        __syncthreads();
    }

    // ---- epilogue ----
    const int cb = wn * 32 + (lane & 3) * 2;
    float2 bias[4];
    if (RELU) {
        #pragma unroll
        for (int j = 0; j < 4; j++) bias[j] = *(const float2*)(br + cb + j * 8);
    }
    const int rbase = m0 + wm * 64 + (lane >> 2);
    #pragma unroll
    for (int i = 0; i < 4; i++) {
        #pragma unroll
        for (int half = 0; half < 2; half++) {
            int r = rbase + i * 16 + half * 8;
            if (r < M) {
                float* outp = C + (size_t)r * DO;
                #pragma unroll
                for (int j = 0; j < 4; j++) {
                    float vx = acc[i][j][half * 2 + 0];
                    float vy = acc[i][j][half * 2 + 1];
                    if (RELU) {
                        vx = fmaxf(vx + bias[j].x, 0.f);
                        vy = fmaxf(vy + bias[j].y, 0.f);
                    }
                    *(float2*)(outp + cb + j * 8) = make_float2(vx, vy);
                }
            }
        }
    }
}

// ---------------- fused final: relu(agg_u + br2 + v) then log_softmax ------
__global__ void final_kernel(const float* __restrict__ aggu,
                             const float* __restrict__ uv,
                             const float* __restrict__ br,
                             float* __restrict__ out, int M) {
    int row = blockIdx.x * 8 + (threadIdx.x >> 5);
    if (row >= M) return;
    int lane = threadIdx.x & 31;
    float2 u = *(const float2*)(aggu + (size_t)row * 64 + lane * 2);
    float2 w = *(const float2*)(uv + (size_t)row * 128 + 64 + lane * 2);
    float2 b = *(const float2*)(br + lane * 2);
    float vx = fmaxf(u.x + w.x + b.x, 0.f);
    float vy = fmaxf(u.y + w.y + b.y, 0.f);
    float mx = fmaxf(vx, vy);
    #pragma unroll
    for (int o = 16; o > 0; o >>= 1)
        mx = fmaxf(mx, __shfl_xor_sync(0xffffffffu, mx, o));
    float s = expf(vx - mx) + expf(vy - mx);
    #pragma unroll
    for (int o = 16; o > 0; o >>= 1)
        s += __shfl_xor_sync(0xffffffffu, s, o);
    float lse = mx + logf(s);
    *(float2*)(out + (size_t)row * 64 + lane * 2) =
        make_float2(vx - lse, vy - lse);
}

// ---------------- launch ----------------------------------------------------
extern "C" void kernel_launch(void* const* d_in, const int* in_sizes, int n_in,
                              void* d_out, int out_size) {
    const float* x   = (const float*)d_in[0];
    const void*  ei  = d_in[1];
    const float* Wr0 = (const float*)d_in[2];
    const float* br0 = (const float*)d_in[3];
    const float* Ws0 = (const float*)d_in[4];
    const float* Wr1 = (const float*)d_in[5];
    const float* br1 = (const float*)d_in[6];
    const float* Ws1 = (const float*)d_in[7];
    const float* Wr2 = (const float*)d_in[8];
    const float* br2 = (const float*)d_in[9];
    const float* Ws2 = (const float*)d_in[10];
    float* out = (float*)d_out;

    const int M = NN;
    const int E = NE;

    float *agg, *h0, *h1;
    cudaGetSymbolAddress((void**)&agg, g_agg);
    cudaGetSymbolAddress((void**)&h0, g_h0);
    cudaGetSymbolAddress((void**)&h1, g_h1);
    __nv_bfloat16 *wh0, *wl0, *wh1, *wl1, *w2h, *w2l;
    cudaGetSymbolAddress((void**)&wh0, g_wh0);
    cudaGetSymbolAddress((void**)&wl0, g_wl0);
    cudaGetSymbolAddress((void**)&wh1, g_wh1);
    cudaGetSymbolAddress((void**)&wl1, g_wl1);
    cudaGetSymbolAddress((void**)&w2h, g_w2h);
    cudaGetSymbolAddress((void**)&w2l, g_w2l);

    const int smemSz = 98304;   // 32K Ahi + 32K Alo + 32K B
    cudaFuncSetAttribute(mma_gemm_kernel<128, 2, true>,
                         cudaFuncAttributeMaxDynamicSharedMemorySize, smemSz);
    cudaFuncSetAttribute(mma_gemm_kernel<128, 1, false>,
                         cudaFuncAttributeMaxDynamicSharedMemorySize, smemSz);

    // Build ELL adjacency + fused weight prep
    zero_cnt_kernel<<<(M + 255) / 256, 256>>>(M);
    detect_kernel<<<1, 32>>>((const int*)ei);
    build_ell_kernel<<<(E + 255) / 256, 256>>>(ei, E);
    prep_all_kernel<<<(65536 + 16384 + 255) / 256, 256>>>(Wr0, Ws0, Wr1, Ws1,
                                                          Wr2, Ws2);

    const int ggrid = (M + 127) / 128;     // 313
    const int agrid = (M + 7) / 8;         // 8 warps/block, 1 node/warp

    // Layer 0: x -> h0
    gather_kernel<<<agrid, 256>>>((const float4*)x, (float4*)agg, M);
    mma_gemm_kernel<128, 2, true><<<ggrid, 256, smemSz>>>(
        agg, x, wh0, wl0, br0, h0, M);

    // Layer 1: h0 -> h1
    gather_kernel<<<agrid, 256>>>((const float4*)h0, (float4*)agg, M);
    mma_gemm_kernel<128, 2, true><<<ggrid, 256, smemSz>>>(
        agg, h0, wh1, wl1, br1, h1, M);

    // Layer 2: uv = h1@[Wr2|Ws2]; gather u (64-dim); fused epilogue+softmax
    mma_gemm_kernel<128, 1, false><<<ggrid, 256, smemSz>>>(
        h1, nullptr, w2h, w2l, nullptr, h0 /*uv*/, M);
    gather_u_kernel<<<(M / 2 + 7) / 8, 256>>>((const float4*)h0, (float4*)agg, M);
    final_kernel<<<(M + 7) / 8, 256>>>(agg, h0, br2, out, M);
}

// round 10
// speedup vs baseline: 1.3692x; 1.1841x over previous
#include <cuda_runtime.h>
#include <cuda_fp16.h>
#include <cstdint>

// Problem constants
#define NN   40000
#define NE   640000
#define DIM  128
#define DO2  64
#define ELLW 64      // max in-degree capacity (Poisson(16) over 40k nodes: safe)

// ---------------- scratch (device globals; no allocation allowed) ----------
__device__ float g_agg[NN * DIM];
__device__ float g_h0[NN * DIM];    // h0; later reused as uv = h1@[Wr2|Ws2]
__device__ float g_h1[NN * DIM];
__device__ int   g_ell[NN * ELLW];
__device__ int   g_cnt[NN];
__device__ int   g_edge64;
// transposed + fp16-split weights, layout [n][k]
__device__ __half g_wh0[128 * 256], g_wl0[128 * 256];  // k=256 (Wr|Ws)
__device__ __half g_wh1[128 * 256], g_wl1[128 * 256];
__device__ __half g_w2h[128 * 128], g_w2l[128 * 128];  // n=[u:64|v:64], k=128

// ---------------- helpers ---------------------------------------------------
__device__ __forceinline__ uint32_t smem_u32(const void* p) {
    uint32_t a;
    asm("{ .reg .u64 t; cvta.to.shared.u64 t, %1; cvt.u32.u64 %0, t; }"
        : "=r"(a) : "l"(p));
    return a;
}

// mma.sync m16n8k16 fp16 -> f32
__device__ __forceinline__ void mma_f16(float* c, const uint32_t* a,
                                        const uint32_t* b) {
    asm volatile(
        "mma.sync.aligned.m16n8k16.row.col.f32.f16.f16.f32 "
        "{%0,%1,%2,%3}, {%4,%5,%6,%7}, {%8,%9}, {%0,%1,%2,%3};"
        : "+f"(c[0]), "+f"(c[1]), "+f"(c[2]), "+f"(c[3])
        : "r"(a[0]), "r"(a[1]), "r"(a[2]), "r"(a[3]), "r"(b[0]), "r"(b[1]));
}

__device__ __forceinline__ void ldm4(uint32_t* r, uint32_t addr) {
    asm volatile("ldmatrix.sync.aligned.m8n8.x4.shared.b16 {%0,%1,%2,%3}, [%4];"
                 : "=r"(r[0]), "=r"(r[1]), "=r"(r[2]), "=r"(r[3]) : "r"(addr));
}

// Swizzled smem offset for a 256B-row fp16 tile (k0 = element col, mult of 4).
__device__ __forceinline__ uint32_t sw_off(int r, int k0) {
    return (uint32_t)r * 256u + ((uint32_t)(((k0 >> 3) ^ (r & 7)) << 4))
         + (uint32_t)((k0 & 4) << 1);
}

// ---------------- edge index dtype detection -------------------------------
__global__ void detect_kernel(const int* __restrict__ ei32) {
    if (blockIdx.x == 0 && threadIdx.x == 0) {
        int is64 = 1;
        #pragma unroll 1
        for (int i = 0; i < 64; i++) {
            if (ei32[2 * i + 1] != 0) { is64 = 0; break; }
        }
        g_edge64 = is64;
    }
}

__global__ void zero_cnt_kernel(int n) {
    int i = blockIdx.x * blockDim.x + threadIdx.x;
    if (i < n) g_cnt[i] = 0;
}

__global__ void build_ell_kernel(const void* __restrict__ ei, int E) {
    int i = blockIdx.x * blockDim.x + threadIdx.x;
    if (i >= E) return;
    int s, d;
    if (g_edge64) {
        const long long* p = (const long long*)ei;
        s = (int)p[i];
        d = (int)p[E + i];
    } else {
        const int* p = (const int*)ei;
        s = p[i];
        d = p[E + i];
    }
    int slot = atomicAdd(&g_cnt[d], 1);
    g_ell[d * ELLW + slot] = s;
}

// ---------------- fused weight prep (fp16 hi/lo, all layers) ---------------
__global__ void prep_all_kernel(const float* __restrict__ Wr0,
                                const float* __restrict__ Ws0,
                                const float* __restrict__ Wr1,
                                const float* __restrict__ Ws1,
                                const float* __restrict__ Wr2,
                                const float* __restrict__ Ws2) {
    int i = blockIdx.x * blockDim.x + threadIdx.x;
    float w;
    __half* Wh;
    __half* Wl;
    size_t off;
    if (i < 65536) {
        int j = i & 32767;
        int k = j % 256;
        int n = j / 256;
        const float* Wr = (i < 32768) ? Wr0 : Wr1;
        const float* Ws = (i < 32768) ? Ws0 : Ws1;
        w = (k < 128) ? Wr[(size_t)k * 128 + n] : Ws[(size_t)(k - 128) * 128 + n];
        Wh = (i < 32768) ? g_wh0 : g_wh1;
        Wl = (i < 32768) ? g_wl0 : g_wl1;
        off = (size_t)n * 256 + k;
    } else if (i < 65536 + 16384) {
        int j = i - 65536;
        int k = j % 128;
        int n = j / 128;
        w = (n < 64) ? Wr2[(size_t)k * 64 + n] : Ws2[(size_t)k * 64 + (n - 64)];
        Wh = g_w2h;
        Wl = g_w2l;
        off = (size_t)n * 128 + k;
    } else {
        return;
    }
    __half hi = __float2half_rn(w);
    float lo = w - __half2float(hi);
    Wh[off] = hi;
    Wl[off] = __float2half_rn(lo);
}

// ---------------- gather aggregation, 128-dim (one warp per node) ----------
__global__ void gather_kernel(const float4* __restrict__ h4,
                              float4* __restrict__ agg, int M) {
    int node = blockIdx.x * (blockDim.x >> 5) + (threadIdx.x >> 5);
    if (node >= M) return;
    int lane = threadIdx.x & 31;
    int deg = g_cnt[node];
    const int* __restrict__ idx = g_ell + node * ELLW;
    float4 acc = make_float4(0.f, 0.f, 0.f, 0.f);
    int i = 0;
    for (; i + 3 < deg; i += 4) {
        int4 s4 = *(const int4*)(idx + i);
        float4 v0 = __ldg(&h4[(size_t)s4.x * 32 + lane]);
        float4 v1 = __ldg(&h4[(size_t)s4.y * 32 + lane]);
        float4 v2 = __ldg(&h4[(size_t)s4.z * 32 + lane]);
        float4 v3 = __ldg(&h4[(size_t)s4.w * 32 + lane]);
        acc.x += (v0.x + v1.x) + (v2.x + v3.x);
        acc.y += (v0.y + v1.y) + (v2.y + v3.y);
        acc.z += (v0.z + v1.z) + (v2.z + v3.z);
        acc.w += (v0.w + v1.w) + (v2.w + v3.w);
    }
    for (; i < deg; i++) {
        int s0 = idx[i];
        float4 v0 = __ldg(&h4[(size_t)s0 * 32 + lane]);
        acc.x += v0.x; acc.y += v0.y; acc.z += v0.z; acc.w += v0.w;
    }
    agg[(size_t)node * 32 + lane] = acc;
}

// ---------------- mma.sync GEMM (fp16, asymmetric 2-term) ------------------
// A single fp16 plane (on-the-fly fp32->fp16); B = precomputed fp16 hi+lo.
// D = A@Bh + A@Bl.
// CHUNKS=2: C = relu(A0@W[0:128] + A1@W[128:256] + br)   (layers 0/1)
// CHUNKS=1: C = A0@W                                     (layer 2, raw)
template <int DO, int CHUNKS, bool RELU>
__global__ void __launch_bounds__(256, 2)
mma_gemm_kernel(const float* __restrict__ A0, const float* __restrict__ A1,
                const __half* __restrict__ Wh, const __half* __restrict__ Wl,
                const float* __restrict__ br, float* __restrict__ C, int M) {
    constexpr int KTOT = CHUNKS * 128;
    constexpr int WN = DO / 32;             // 4 for DO=128
    constexpr int THREADS = 256;
    constexpr int A_SM = 0;                 // 32KB
    constexpr int B_HI = 32768;             // 32KB
    constexpr int B_LO = 65536;             // 32KB

    extern __shared__ char smem[];
    const uint32_t sb = smem_u32(smem);
    const int tid = threadIdx.x;
    const int lane = tid & 31;
    const int wid = tid >> 5;
    const int wm = wid / WN;                // 0..1
    const int wn = wid % WN;
    const int m0 = blockIdx.x * 128;

    float acc[4][4][4];
    #pragma unroll
    for (int i = 0; i < 4; i++)
        #pragma unroll
        for (int j = 0; j < 4; j++)
            #pragma unroll
            for (int q = 0; q < 4; q++) acc[i][j][q] = 0.f;

    #pragma unroll 1
    for (int ch = 0; ch < CHUNKS; ch++) {
        const float* __restrict__ Asrc = ch ? A1 : A0;

        // ---- fill A (fp32 -> fp16, swizzled): 128 rows x 128 cols ----
        #pragma unroll
        for (int t = 0; t < 4096 / THREADS; t++) {
            int f = tid + t * THREADS;
            int row = f >> 5;
            int k0 = (f & 31) * 4;
            int gm = m0 + row;
            float4 v = make_float4(0.f, 0.f, 0.f, 0.f);
            if (gm < M) v = *(const float4*)(Asrc + (size_t)gm * DIM + k0);
            __half2 h01 = __float22half2_rn(make_float2(v.x, v.y));
            __half2 h23 = __float22half2_rn(make_float2(v.z, v.w));
            *(uint2*)(smem + A_SM + sw_off(row, k0)) =
                make_uint2(*(uint32_t*)&h01, *(uint32_t*)&h23);
        }
        // ---- fill B hi+lo planes (pure 16B copies) ----
        #pragma unroll
        for (int t = 0; t < (DO * 16) / THREADS; t++) {
            int f = tid + t * THREADS;
            int n = f >> 4;
            int g = f & 15;
            uint32_t off = (uint32_t)n * 256u + (uint32_t)((g ^ (n & 7)) << 4);
            *(uint4*)(smem + B_HI + off) =
                *(const uint4*)(Wh + (size_t)n * KTOT + ch * 128 + g * 8);
            *(uint4*)(smem + B_LO + off) =
                *(const uint4*)(Wl + (size_t)n * KTOT + ch * 128 + g * 8);
        }
        __syncthreads();

        // ---- MMA over 8 k16-steps: A*Bh + A*Bl ----
        #pragma unroll
        for (int ks = 0; ks < 8; ks++) {
            uint32_t aa[4][4], bh[2][4], bl[2][4];
            int ra = wm * 64 + (lane & 15);
            int hc = (lane >> 4) & 1;
            #pragma unroll
            for (int i = 0; i < 4; i++) {
                int r = ra + i * 16;
                uint32_t ad = sb + A_SM + (uint32_t)r * 256
                            + (uint32_t)((((ks * 2 + hc) ^ (r & 7))) << 4);
                ldm4(aa[i], ad);
            }
            int nn = (lane & 7) | ((lane & 16) >> 1);
            int hb = (lane >> 3) & 1;
            #pragma unroll
            for (int p = 0; p < 2; p++) {
                int n = wn * 32 + p * 16 + nn;
                uint32_t bd = sb + B_HI + (uint32_t)n * 256
                            + (uint32_t)((((ks * 2 + hb) ^ (n & 7))) << 4);
                ldm4(bh[p], bd);
                ldm4(bl[p], bd + (B_LO - B_HI));
            }
            #pragma unroll
            for (int i = 0; i < 4; i++)
                #pragma unroll
                for (int j = 0; j < 4; j++) {
                    mma_f16(acc[i][j], aa[i], &bh[j >> 1][(j & 1) * 2]);
                    mma_f16(acc[i][j], aa[i], &bl[j >> 1][(j & 1) * 2]);
                }
        }
        __syncthreads();
    }

    // ---- epilogue ----
    const int cb = wn * 32 + (lane & 3) * 2;
    float2 bias[4];
    if (RELU) {
        #pragma unroll
        for (int j = 0; j < 4; j++) bias[j] = *(const float2*)(br + cb + j * 8);
    }
    const int rbase = m0 + wm * 64 + (lane >> 2);
    #pragma unroll
    for (int i = 0; i < 4; i++) {
        #pragma unroll
        for (int half = 0; half < 2; half++) {
            int r = rbase + i * 16 + half * 8;
            if (r < M) {
                float* outp = C + (size_t)r * DO;
                #pragma unroll
                for (int j = 0; j < 4; j++) {
                    float vx = acc[i][j][half * 2 + 0];
                    float vy = acc[i][j][half * 2 + 1];
                    if (RELU) {
                        vx = fmaxf(vx + bias[j].x, 0.f);
                        vy = fmaxf(vy + bias[j].y, 0.f);
                    }
                    *(float2*)(outp + cb + j * 8) = make_float2(vx, vy);
                }
            }
        }
    }
}

// ---------------- fused final: gather u + relu(u+v+br2) + log_softmax ------
// One warp per node; each lane covers 2 of the 64 output cols (float2).
__global__ void final_kernel(const float* __restrict__ uv,
                             const float* __restrict__ br,
                             float* __restrict__ out, int M) {
    int node = blockIdx.x * (blockDim.x >> 5) + (threadIdx.x >> 5);
    if (node >= M) return;
    int lane = threadIdx.x & 31;
    int deg = g_cnt[node];
    const int* __restrict__ idx = g_ell + node * ELLW;
    const float2* __restrict__ uv2 = (const float2*)uv;
    float2 acc = make_float2(0.f, 0.f);
    int i = 0;
    for (; i + 3 < deg; i += 4) {
        int4 s4 = *(const int4*)(idx + i);
        float2 v0 = __ldg(&uv2[(size_t)s4.x * 64 + lane]);
        float2 v1 = __ldg(&uv2[(size_t)s4.y * 64 + lane]);
        float2 v2 = __ldg(&uv2[(size_t)s4.z * 64 + lane]);
        float2 v3 = __ldg(&uv2[(size_t)s4.w * 64 + lane]);
        acc.x += (v0.x + v1.x) + (v2.x + v3.x);
        acc.y += (v0.y + v1.y) + (v2.y + v3.y);
    }
    for (; i < deg; i++) {
        float2 v0 = __ldg(&uv2[(size_t)idx[i] * 64 + lane]);
        acc.x += v0.x; acc.y += v0.y;
    }
    float2 w = __ldg(&uv2[(size_t)node * 64 + 32 + lane]);   // v part (cols 64..127)
    float2 b = *(const float2*)(br + lane * 2);
    float vx = fmaxf(acc.x + w.x + b.x, 0.f);
    float vy = fmaxf(acc.y + w.y + b.y, 0.f);
    float mx = fmaxf(vx, vy);
    #pragma unroll
    for (int o = 16; o > 0; o >>= 1)
        mx = fmaxf(mx, __shfl_xor_sync(0xffffffffu, mx, o));
    float s = expf(vx - mx) + expf(vy - mx);
    #pragma unroll
    for (int o = 16; o > 0; o >>= 1)
        s += __shfl_xor_sync(0xffffffffu, s, o);
    float lse = mx + logf(s);
    *(float2*)(out + (size_t)node * 64 + lane * 2) =
        make_float2(vx - lse, vy - lse);
}

// ---------------- launch ----------------------------------------------------
extern "C" void kernel_launch(void* const* d_in, const int* in_sizes, int n_in,
                              void* d_out, int out_size) {
    const float* x   = (const float*)d_in[0];
    const void*  ei  = d_in[1];
    const float* Wr0 = (const float*)d_in[2];
    const float* br0 = (const float*)d_in[3];
    const float* Ws0 = (const float*)d_in[4];
    const float* Wr1 = (const float*)d_in[5];
    const float* br1 = (const float*)d_in[6];
    const float* Ws1 = (const float*)d_in[7];
    const float* Wr2 = (const float*)d_in[8];
    const float* br2 = (const float*)d_in[9];
    const float* Ws2 = (const float*)d_in[10];
    float* out = (float*)d_out;

    const int M = NN;
    const int E = NE;

    float *agg, *h0, *h1;
    cudaGetSymbolAddress((void**)&agg, g_agg);
    cudaGetSymbolAddress((void**)&h0, g_h0);
    cudaGetSymbolAddress((void**)&h1, g_h1);
    __half *wh0, *wl0, *wh1, *wl1, *w2h, *w2l;
    cudaGetSymbolAddress((void**)&wh0, g_wh0);
    cudaGetSymbolAddress((void**)&wl0, g_wl0);
    cudaGetSymbolAddress((void**)&wh1, g_wh1);
    cudaGetSymbolAddress((void**)&wl1, g_wl1);
    cudaGetSymbolAddress((void**)&w2h, g_w2h);
    cudaGetSymbolAddress((void**)&w2l, g_w2l);

    const int smemSz = 98304;   // 32K A + 32K Bh + 32K Bl
    cudaFuncSetAttribute(mma_gemm_kernel<128, 2, true>,
                         cudaFuncAttributeMaxDynamicSharedMemorySize, smemSz);
    cudaFuncSetAttribute(mma_gemm_kernel<128, 1, false>,
                         cudaFuncAttributeMaxDynamicSharedMemorySize, smemSz);

    // Build ELL adjacency + fused weight prep
    zero_cnt_kernel<<<(M + 255) / 256, 256>>>(M);
    detect_kernel<<<1, 32>>>((const int*)ei);
    build_ell_kernel<<<(E + 255) / 256, 256>>>(ei, E);
    prep_all_kernel<<<(65536 + 16384 + 255) / 256, 256>>>(Wr0, Ws0, Wr1, Ws1,
                                                          Wr2, Ws2);

    const int ggrid = (M + 127) / 128;     // 313
    const int agrid = (M + 7) / 8;         // 8 warps/block, 1 node/warp

    // Layer 0: x -> h0
    gather_kernel<<<agrid, 256>>>((const float4*)x, (float4*)agg, M);
    mma_gemm_kernel<128, 2, true><<<ggrid, 256, smemSz>>>(
        agg, x, wh0, wl0, br0, h0, M);

    // Layer 1: h0 -> h1
    gather_kernel<<<agrid, 256>>>((const float4*)h0, (float4*)agg, M);
    mma_gemm_kernel<128, 2, true><<<ggrid, 256, smemSz>>>(
        agg, h0, wh1, wl1, br1, h1, M);

    // Layer 2: uv = h1@[Wr2|Ws2]; fused gather-u + epilogue + log_softmax
    mma_gemm_kernel<128, 1, false><<<ggrid, 256, smemSz>>>(
        h1, nullptr, w2h, w2l, nullptr, h0 /*uv*/, M);
    final_kernel<<<agrid, 256>>>(h0, br2, out, M);
}

// round 11
// speedup vs baseline: 1.5272x; 1.1154x over previous
#include <cuda_runtime.h>
#include <cuda_fp16.h>
#include <cstdint>

// Problem constants
#define NN   40000
#define NE   640000
#define DIM  128
#define DO2  64
#define ELLW 64      // max in-degree capacity (Poisson(16) over 40k nodes: safe)

// ---------------- scratch (device globals; no allocation allowed) ----------
// All feature matrices in fp16 (the MMA consumes fp16 A anyway).
__device__ __half g_x16[NN * DIM];
__device__ __half g_agg16[NN * DIM];
__device__ __half g_h016[NN * DIM];   // h0; later reused as uv = h1@[Wr2|Ws2]
__device__ __half g_h116[NN * DIM];
__device__ int   g_ell[NN * ELLW];
__device__ int   g_cnt[NN];
__device__ int   g_edge64;
// transposed + fp16-split weights, layout [n][k]
__device__ __half g_wh0[128 * 256], g_wl0[128 * 256];  // k=256 (Wr|Ws)
__device__ __half g_wh1[128 * 256], g_wl1[128 * 256];
__device__ __half g_w2h[128 * 128], g_w2l[128 * 128];  // n=[u:64|v:64], k=128

// ---------------- helpers ---------------------------------------------------
__device__ __forceinline__ uint32_t smem_u32(const void* p) {
    uint32_t a;
    asm("{ .reg .u64 t; cvta.to.shared.u64 t, %1; cvt.u32.u64 %0, t; }"
        : "=r"(a) : "l"(p));
    return a;
}

// mma.sync m16n8k16 fp16 -> f32
__device__ __forceinline__ void mma_f16(float* c, const uint32_t* a,
                                        const uint32_t* b) {
    asm volatile(
        "mma.sync.aligned.m16n8k16.row.col.f32.f16.f16.f32 "
        "{%0,%1,%2,%3}, {%4,%5,%6,%7}, {%8,%9}, {%0,%1,%2,%3};"
        : "+f"(c[0]), "+f"(c[1]), "+f"(c[2]), "+f"(c[3])
        : "r"(a[0]), "r"(a[1]), "r"(a[2]), "r"(a[3]), "r"(b[0]), "r"(b[1]));
}

__device__ __forceinline__ void ldm4(uint32_t* r, uint32_t addr) {
    asm volatile("ldmatrix.sync.aligned.m8n8.x4.shared.b16 {%0,%1,%2,%3}, [%4];"
                 : "=r"(r[0]), "=r"(r[1]), "=r"(r[2]), "=r"(r[3]) : "r"(addr));
}

// ---------------- edge index dtype detection -------------------------------
__global__ void detect_kernel(const int* __restrict__ ei32) {
    if (blockIdx.x == 0 && threadIdx.x == 0) {
        int is64 = 1;
        #pragma unroll 1
        for (int i = 0; i < 64; i++) {
            if (ei32[2 * i + 1] != 0) { is64 = 0; break; }
        }
        g_edge64 = is64;
    }
}

__global__ void zero_cnt_kernel(int n) {
    int i = blockIdx.x * blockDim.x + threadIdx.x;
    if (i < n) g_cnt[i] = 0;
}

__global__ void build_ell_kernel(const void* __restrict__ ei, int E) {
    int i = blockIdx.x * blockDim.x + threadIdx.x;
    if (i >= E) return;
    int s, d;
    if (g_edge64) {
        const long long* p = (const long long*)ei;
        s = (int)p[i];
        d = (int)p[E + i];
    } else {
        const int* p = (const int*)ei;
        s = p[i];
        d = p[E + i];
    }
    int slot = atomicAdd(&g_cnt[d], 1);
    g_ell[d * ELLW + slot] = s;
}

// ---------------- fused weight prep (fp16 hi/lo, all layers) ---------------
__global__ void prep_all_kernel(const float* __restrict__ Wr0,
                                const float* __restrict__ Ws0,
                                const float* __restrict__ Wr1,
                                const float* __restrict__ Ws1,
                                const float* __restrict__ Wr2,
                                const float* __restrict__ Ws2) {
    int i = blockIdx.x * blockDim.x + threadIdx.x;
    float w;
    __half* Wh;
    __half* Wl;
    size_t off;
    if (i < 65536) {
        int j = i & 32767;
        int k = j % 256;
        int n = j / 256;
        const float* Wr = (i < 32768) ? Wr0 : Wr1;
        const float* Ws = (i < 32768) ? Ws0 : Ws1;
        w = (k < 128) ? Wr[(size_t)k * 128 + n] : Ws[(size_t)(k - 128) * 128 + n];
        Wh = (i < 32768) ? g_wh0 : g_wh1;
        Wl = (i < 32768) ? g_wl0 : g_wl1;
        off = (size_t)n * 256 + k;
    } else if (i < 65536 + 16384) {
        int j = i - 65536;
        int k = j % 128;
        int n = j / 128;
        w = (n < 64) ? Wr2[(size_t)k * 64 + n] : Ws2[(size_t)k * 64 + (n - 64)];
        Wh = g_w2h;
        Wl = g_w2l;
        off = (size_t)n * 128 + k;
    } else {
        return;
    }
    __half hi = __float2half_rn(w);
    float lo = w - __half2float(hi);
    Wh[off] = hi;
    Wl[off] = __float2half_rn(lo);
}

// ---------------- convert x fp32 -> fp16 ------------------------------------
__global__ void cvt_x_kernel(const float4* __restrict__ x4,
                             uint2* __restrict__ x16, int n4) {
    int i = blockIdx.x * blockDim.x + threadIdx.x;
    if (i >= n4) return;
    float4 v = x4[i];
    __half2 a = __float22half2_rn(make_float2(v.x, v.y));
    __half2 b = __float22half2_rn(make_float2(v.z, v.w));
    x16[i] = make_uint2(*(uint32_t*)&a, *(uint32_t*)&b);
}

// ---------------- gather aggregation, fp16 in / fp16 out -------------------
// One warp per node; lane covers 4 dims (uint2 = 4 halves = 8B per neighbor).
__global__ void gather_kernel(const uint2* __restrict__ h16,
                              uint2* __restrict__ agg, int M) {
    int node = blockIdx.x * (blockDim.x >> 5) + (threadIdx.x >> 5);
    if (node >= M) return;
    int lane = threadIdx.x & 31;
    int deg = g_cnt[node];
    const int* __restrict__ idx = g_ell + node * ELLW;
    float4 acc = make_float4(0.f, 0.f, 0.f, 0.f);

    auto addrow = [&](int s) {
        uint2 v = __ldg(&h16[(size_t)s * 32 + lane]);
        float2 a = __half22float2(*(__half2*)&v.x);
        float2 b = __half22float2(*(__half2*)&v.y);
        acc.x += a.x; acc.y += a.y; acc.z += b.x; acc.w += b.y;
    };

    int i = 0;
    for (; i + 3 < deg; i += 4) {
        int4 s4 = *(const int4*)(idx + i);
        addrow(s4.x); addrow(s4.y); addrow(s4.z); addrow(s4.w);
    }
    for (; i < deg; i++) addrow(idx[i]);

    __half2 a = __float22half2_rn(make_float2(acc.x, acc.y));
    __half2 b = __float22half2_rn(make_float2(acc.z, acc.w));
    agg[(size_t)node * 32 + lane] = make_uint2(*(uint32_t*)&a, *(uint32_t*)&b);
}

// ---------------- mma.sync GEMM (fp16 A, B=hi+lo 2-term) -------------------
// CHUNKS=2: C = relu(A0@W[0:128] + A1@W[128:256] + br)   (layers 0/1)
// CHUNKS=1: C = A0@W                                     (layer 2, raw)
template <int DO, int CHUNKS, bool RELU>
__global__ void __launch_bounds__(256, 2)
mma_gemm_kernel(const __half* __restrict__ A0, const __half* __restrict__ A1,
                const __half* __restrict__ Wh, const __half* __restrict__ Wl,
                const float* __restrict__ br, __half* __restrict__ C, int M) {
    constexpr int KTOT = CHUNKS * 128;
    constexpr int WN = DO / 32;             // 4 for DO=128
    constexpr int THREADS = 256;
    constexpr int A_SM = 0;                 // 32KB
    constexpr int B_HI = 32768;             // 32KB
    constexpr int B_LO = 65536;             // 32KB

    extern __shared__ char smem[];
    const uint32_t sb = smem_u32(smem);
    const int tid = threadIdx.x;
    const int lane = tid & 31;
    const int wid = tid >> 5;
    const int wm = wid / WN;                // 0..1
    const int wn = wid % WN;
    const int m0 = blockIdx.x * 128;

    float acc[4][4][4];
    #pragma unroll
    for (int i = 0; i < 4; i++)
        #pragma unroll
        for (int j = 0; j < 4; j++)
            #pragma unroll
            for (int q = 0; q < 4; q++) acc[i][j][q] = 0.f;

    #pragma unroll 1
    for (int ch = 0; ch < CHUNKS; ch++) {
        const __half* __restrict__ Asrc = ch ? A1 : A0;

        // ---- fill A (pure swizzled 16B copy): 128 rows x 16 granules ----
        #pragma unroll
        for (int t = 0; t < 8; t++) {
            int f = tid + t * THREADS;      // 0..2047
            int row = f >> 4;
            int g = f & 15;
            int gm = m0 + row;
            uint4 v = make_uint4(0u, 0u, 0u, 0u);
            if (gm < M) v = *(const uint4*)(Asrc + (size_t)gm * DIM + g * 8);
            uint32_t off = (uint32_t)row * 256u + (uint32_t)((g ^ (row & 7)) << 4);
            *(uint4*)(smem + A_SM + off) = v;
        }
        // ---- fill B hi+lo planes (pure 16B copies) ----
        #pragma unroll
        for (int t = 0; t < (DO * 16) / THREADS; t++) {
            int f = tid + t * THREADS;
            int n = f >> 4;
            int g = f & 15;
            uint32_t off = (uint32_t)n * 256u + (uint32_t)((g ^ (n & 7)) << 4);
            *(uint4*)(smem + B_HI + off) =
                *(const uint4*)(Wh + (size_t)n * KTOT + ch * 128 + g * 8);
            *(uint4*)(smem + B_LO + off) =
                *(const uint4*)(Wl + (size_t)n * KTOT + ch * 128 + g * 8);
        }
        __syncthreads();

        // ---- MMA over 8 k16-steps: A*Bh + A*Bl ----
        #pragma unroll
        for (int ks = 0; ks < 8; ks++) {
            uint32_t aa[4][4], bh[2][4], bl[2][4];
            int ra = wm * 64 + (lane & 15);
            int hc = (lane >> 4) & 1;
            #pragma unroll
            for (int i = 0; i < 4; i++) {
                int r = ra + i * 16;
                uint32_t ad = sb + A_SM + (uint32_t)r * 256
                            + (uint32_t)((((ks * 2 + hc) ^ (r & 7))) << 4);
                ldm4(aa[i], ad);
            }
            int nn = (lane & 7) | ((lane & 16) >> 1);
            int hb = (lane >> 3) & 1;
            #pragma unroll
            for (int p = 0; p < 2; p++) {
                int n = wn * 32 + p * 16 + nn;
                uint32_t bd = sb + B_HI + (uint32_t)n * 256
                            + (uint32_t)((((ks * 2 + hb) ^ (n & 7))) << 4);
                ldm4(bh[p], bd);
                ldm4(bl[p], bd + (B_LO - B_HI));
            }
            #pragma unroll
            for (int i = 0; i < 4; i++)
                #pragma unroll
                for (int j = 0; j < 4; j++) {
                    mma_f16(acc[i][j], aa[i], &bh[j >> 1][(j & 1) * 2]);
                    mma_f16(acc[i][j], aa[i], &bl[j >> 1][(j & 1) * 2]);
                }
        }
        __syncthreads();
    }

    // ---- epilogue: (+bias, relu), fp16 store ----
    const int cb = wn * 32 + (lane & 3) * 2;
    float2 bias[4];
    if (RELU) {
        #pragma unroll
        for (int j = 0; j < 4; j++) bias[j] = *(const float2*)(br + cb + j * 8);
    }
    const int rbase = m0 + wm * 64 + (lane >> 2);
    #pragma unroll
    for (int i = 0; i < 4; i++) {
        #pragma unroll
        for (int half = 0; half < 2; half++) {
            int r = rbase + i * 16 + half * 8;
            if (r < M) {
                __half* outp = C + (size_t)r * DO;
                #pragma unroll
                for (int j = 0; j < 4; j++) {
                    float vx = acc[i][j][half * 2 + 0];
                    float vy = acc[i][j][half * 2 + 1];
                    if (RELU) {
                        vx = fmaxf(vx + bias[j].x, 0.f);
                        vy = fmaxf(vy + bias[j].y, 0.f);
                    }
                    __half2 h = __float22half2_rn(make_float2(vx, vy));
                    *(uint32_t*)(outp + cb + j * 8) = *(uint32_t*)&h;
                }
            }
        }
    }
}

// ---------------- fused final: gather u + relu(u+v+br2) + log_softmax ------
// One warp per node; lane covers 2 of 64 cols (half2 = 4B per neighbor).
__global__ void final_kernel(const __half2* __restrict__ uv2,
                             const float* __restrict__ br,
                             float* __restrict__ out, int M) {
    int node = blockIdx.x * (blockDim.x >> 5) + (threadIdx.x >> 5);
    if (node >= M) return;
    int lane = threadIdx.x & 31;
    int deg = g_cnt[node];
    const int* __restrict__ idx = g_ell + node * ELLW;
    float2 acc = make_float2(0.f, 0.f);

    auto addrow = [&](int s) {
        float2 v = __half22float2(__ldg(&uv2[(size_t)s * 64 + lane]));
        acc.x += v.x; acc.y += v.y;
    };

    int i = 0;
    for (; i + 3 < deg; i += 4) {
        int4 s4 = *(const int4*)(idx + i);
        addrow(s4.x); addrow(s4.y); addrow(s4.z); addrow(s4.w);
    }
    for (; i < deg; i++) addrow(idx[i]);

    float2 w = __half22float2(__ldg(&uv2[(size_t)node * 64 + 32 + lane]));
    float2 b = *(const float2*)(br + lane * 2);
    float vx = fmaxf(acc.x + w.x + b.x, 0.f);
    float vy = fmaxf(acc.y + w.y + b.y, 0.f);
    float mx = fmaxf(vx, vy);
    #pragma unroll
    for (int o = 16; o > 0; o >>= 1)
        mx = fmaxf(mx, __shfl_xor_sync(0xffffffffu, mx, o));
    float s = expf(vx - mx) + expf(vy - mx);
    #pragma unroll
    for (int o = 16; o > 0; o >>= 1)
        s += __shfl_xor_sync(0xffffffffu, s, o);
    float lse = mx + logf(s);
    *(float2*)(out + (size_t)node * 64 + lane * 2) =
        make_float2(vx - lse, vy - lse);
}

// ---------------- launch ----------------------------------------------------
extern "C" void kernel_launch(void* const* d_in, const int* in_sizes, int n_in,
                              void* d_out, int out_size) {
    const float* x   = (const float*)d_in[0];
    const void*  ei  = d_in[1];
    const float* Wr0 = (const float*)d_in[2];
    const float* br0 = (const float*)d_in[3];
    const float* Ws0 = (const float*)d_in[4];
    const float* Wr1 = (const float*)d_in[5];
    const float* br1 = (const float*)d_in[6];
    const float* Ws1 = (const float*)d_in[7];
    const float* Wr2 = (const float*)d_in[8];
    const float* br2 = (const float*)d_in[9];
    const float* Ws2 = (const float*)d_in[10];
    float* out = (float*)d_out;

    const int M = NN;
    const int E = NE;

    __half *x16, *agg16, *h016, *h116;
    cudaGetSymbolAddress((void**)&x16, g_x16);
    cudaGetSymbolAddress((void**)&agg16, g_agg16);
    cudaGetSymbolAddress((void**)&h016, g_h016);
    cudaGetSymbolAddress((void**)&h116, g_h116);
    __half *wh0, *wl0, *wh1, *wl1, *w2h, *w2l;
    cudaGetSymbolAddress((void**)&wh0, g_wh0);
    cudaGetSymbolAddress((void**)&wl0, g_wl0);
    cudaGetSymbolAddress((void**)&wh1, g_wh1);
    cudaGetSymbolAddress((void**)&wl1, g_wl1);
    cudaGetSymbolAddress((void**)&w2h, g_w2h);
    cudaGetSymbolAddress((void**)&w2l, g_w2l);

    const int smemSz = 98304;   // 32K A + 32K Bh + 32K Bl
    cudaFuncSetAttribute(mma_gemm_kernel<128, 2, true>,
                         cudaFuncAttributeMaxDynamicSharedMemorySize, smemSz);
    cudaFuncSetAttribute(mma_gemm_kernel<128, 1, false>,
                         cudaFuncAttributeMaxDynamicSharedMemorySize, smemSz);

    // Build ELL adjacency + fused weight prep + x convert
    zero_cnt_kernel<<<(M + 255) / 256, 256>>>(M);
    detect_kernel<<<1, 32>>>((const int*)ei);
    build_ell_kernel<<<(E + 255) / 256, 256>>>(ei, E);
    prep_all_kernel<<<(65536 + 16384 + 255) / 256, 256>>>(Wr0, Ws0, Wr1, Ws1,
                                                          Wr2, Ws2);
    cvt_x_kernel<<<(NN * 32 + 255) / 256, 256>>>((const float4*)x,
                                                 (uint2*)x16, NN * 32);

    const int ggrid = (M + 127) / 128;     // 313
    const int agrid = (M + 7) / 8;         // 8 warps/block, 1 node/warp

    // Layer 0: x -> h0
    gather_kernel<<<agrid, 256>>>((const uint2*)x16, (uint2*)agg16, M);
    mma_gemm_kernel<128, 2, true><<<ggrid, 256, smemSz>>>(
        agg16, x16, wh0, wl0, br0, h016, M);

    // Layer 1: h0 -> h1
    gather_kernel<<<agrid, 256>>>((const uint2*)h016, (uint2*)agg16, M);
    mma_gemm_kernel<128, 2, true><<<ggrid, 256, smemSz>>>(
        agg16, h016, wh1, wl1, br1, h116, M);

    // Layer 2: uv = h1@[Wr2|Ws2] (fp16); fused gather-u + epilogue + softmax
    mma_gemm_kernel<128, 1, false><<<ggrid, 256, smemSz>>>(
        h116, nullptr, w2h, w2l, nullptr, h016 /*uv*/, M);
    final_kernel<<<agrid, 256>>>((const __half2*)h016, br2, out, M);
}